// round 1
// baseline (speedup 1.0000x reference)
#include <cuda_runtime.h>
#include <math.h>

// ---------------- problem constants ----------------
#define Bc   2
#define Sc   2048
#define Hc   1024
#define NHc  16
#define HDc  64
#define MLPc 32
#define Mtot (Bc*Sc)   // 4096

// ---------------- scratch (static device globals; no allocation) ----------------
__device__ float g_Q[(size_t)Bc*NHc*Sc*HDc];     // (B,NH,S,HD)
__device__ float g_K[(size_t)Bc*NHc*Sc*HDc];
__device__ float g_V[(size_t)Bc*NHc*Sc*HDc];
__device__ float g_reach[Bc*NHc*Sc];             // (B,NH,S)
__device__ float g_attract[Bc*NHc*Sc];
__device__ float g_attn[(size_t)Mtot*Hc];        // (B,S,H) attention output
__device__ float g_proj[(size_t)Mtot*Hc];        // (B,S,H) O-projection output

// ---------------- mask MLPs: reach/attract ----------------
__global__ void mask_mlp_kernel(const float* __restrict__ imp,
    const float* __restrict__ rw1, const float* __restrict__ rb1,
    const float* __restrict__ rw2, const float* __restrict__ rb2,
    const float* __restrict__ aw1, const float* __restrict__ ab1,
    const float* __restrict__ aw2, const float* __restrict__ ab2)
{
    int idx = blockIdx.x * blockDim.x + threadIdx.x;
    if (idx >= Bc*Sc) return;
    float x = imp[idx];
    float hr[MLPc], ha[MLPc];
    const float kInvSqrt2 = 0.70710678118654752440f;
    #pragma unroll
    for (int j = 0; j < MLPc; j++) {
        float t = fmaf(x, rw1[j], rb1[j]);
        hr[j] = 0.5f * t * (1.0f + erff(t * kInvSqrt2));
        float u = fmaf(x, aw1[j], ab1[j]);
        ha[j] = 0.5f * u * (1.0f + erff(u * kInvSqrt2));
    }
    int b = idx / Sc, s = idx - b * Sc;
    #pragma unroll
    for (int h = 0; h < NHc; h++) {
        float rs = rb2[h], as = ab2[h];
        #pragma unroll
        for (int j = 0; j < MLPc; j++) {
            rs = fmaf(hr[j], rw2[j*NHc + h], rs);
            as = fmaf(ha[j], aw2[j*NHc + h], as);
        }
        g_reach[(b*NHc + h)*Sc + s]   = rs;
        g_attract[(b*NHc + h)*Sc + s] = as;
    }
}

// ---------------- GEMM: C(4096x1024) = A(4096x1024) @ W(1024x1024) + bias ----------------
// OUTSEL: 0/1/2 -> Q/K/V transposed store (B,NH,S,HD); 3 -> plain store to g_proj (A = g_attn)
template<int OUTSEL>
__global__ __launch_bounds__(256) void gemm_kernel(
    const float* __restrict__ Ain, const float* __restrict__ W,
    const float* __restrict__ bias)
{
    const int Kd = Hc, Nd = Hc;
    const int PAD = 132;
    __shared__ __align__(16) float Ast[16*PAD];   // [k][m] (transposed A tile)
    __shared__ __align__(16) float Wsm[16*PAD];   // [k][n]
    const float* A = (OUTSEL == 3) ? (const float*)g_attn : Ain;
    int m0 = blockIdx.y * 128;
    int n0 = blockIdx.x * 128;
    int tid = threadIdx.x;
    int tx = tid & 15;     // n octet
    int ty = tid >> 4;     // m octet
    float acc[8][8];
    #pragma unroll
    for (int i = 0; i < 8; i++)
        #pragma unroll
        for (int j = 0; j < 8; j++) acc[i][j] = 0.f;

    for (int k0 = 0; k0 < Kd; k0 += 16) {
        __syncthreads();
        #pragma unroll
        for (int l = 0; l < 8; l++) {
            int i = tid + l*256;                 // 0..2047
            int cA = i & 15, rA = i >> 4;        // A tile 128x16
            Ast[cA*PAD + rA] = A[(size_t)(m0 + rA)*Kd + k0 + cA];
            int cW = i >> 7, nW = i & 127;       // W tile 16x128
            Wsm[cW*PAD + nW] = W[(size_t)(k0 + cW)*Nd + n0 + nW];
        }
        __syncthreads();
        #pragma unroll
        for (int kk = 0; kk < 16; kk++) {
            float4 a0 = *reinterpret_cast<const float4*>(&Ast[kk*PAD + ty*8]);
            float4 a1 = *reinterpret_cast<const float4*>(&Ast[kk*PAD + ty*8 + 4]);
            float4 b0 = *reinterpret_cast<const float4*>(&Wsm[kk*PAD + tx*8]);
            float4 b1 = *reinterpret_cast<const float4*>(&Wsm[kk*PAD + tx*8 + 4]);
            float a[8] = {a0.x,a0.y,a0.z,a0.w,a1.x,a1.y,a1.z,a1.w};
            float bb[8] = {b0.x,b0.y,b0.z,b0.w,b1.x,b1.y,b1.z,b1.w};
            #pragma unroll
            for (int i = 0; i < 8; i++)
                #pragma unroll
                for (int j = 0; j < 8; j++)
                    acc[i][j] = fmaf(a[i], bb[j], acc[i][j]);
        }
    }

    #pragma unroll
    for (int i = 0; i < 8; i++) {
        int m = m0 + ty*8 + i;
        #pragma unroll
        for (int jq = 0; jq < 2; jq++) {
            int n = n0 + tx*8 + jq*4;
            float4 bv = *reinterpret_cast<const float4*>(&bias[n]);
            float4 v;
            v.x = acc[i][jq*4+0] + bv.x;
            v.y = acc[i][jq*4+1] + bv.y;
            v.z = acc[i][jq*4+2] + bv.z;
            v.w = acc[i][jq*4+3] + bv.w;
            if (OUTSEL < 3) {
                int bb2 = m >> 11;       // / S
                int ss  = m & 2047;
                int hh  = n >> 6;
                int dd  = n & 63;
                float* outp = (OUTSEL == 0) ? g_Q : (OUTSEL == 1) ? g_K : g_V;
                *reinterpret_cast<float4*>(
                    &outp[(((size_t)bb2*NHc + hh)*Sc + ss)*HDc + dd]) = v;
            } else {
                *reinterpret_cast<float4*>(&g_proj[(size_t)m*Nd + n]) = v;
            }
        }
    }
}

// ---------------- flash attention with on-the-fly mask bias ----------------
// grid (S/64, 1, B*NH), 256 threads; 64q x 64k tiles, 4x4 register blocking.
#define FL_SMEM_FLOATS (4*64*65)
__global__ __launch_bounds__(256) void flash_kernel(const float* __restrict__ log_temp)
{
    extern __shared__ float sm[];
    float* Qs = sm;              // [64][65]
    float* Ks = sm + 64*65;
    float* Vs = sm + 2*64*65;
    float* Ps = sm + 3*64*65;

    int bh = blockIdx.z;
    int b = bh >> 4;
    int h = bh & 15;
    int q0 = blockIdx.x * 64;
    int tid = threadIdx.x;
    int tx = tid & 15;    // key quad (4 keys)
    int ty = tid >> 4;    // row quad (4 rows)

    const float* Qg  = g_Q + ((size_t)bh*Sc + q0) * HDc;
    const float* Kg  = g_K + (size_t)bh*Sc*HDc;
    const float* Vg  = g_V + (size_t)bh*Sc*HDc;
    const float* att = g_attract + bh*Sc;

    for (int i = tid; i < 64*64; i += 256) {
        int rr = i >> 6, dd = i & 63;
        Qs[rr*65 + dd] = Qg[rr*64 + dd];
    }

    float reachv[4], qposf[4];
    #pragma unroll
    for (int i = 0; i < 4; i++) {
        reachv[i] = g_reach[bh*Sc + q0 + ty*4 + i];
        qposf[i]  = (float)(q0 + ty*4 + i);
    }
    float temp   = __expf(log_temp[h]) + 1.0f;
    float inv_st = 1.0f / ((float)Sc * temp);

    float mrow[4], lrow[4], O[4][4];
    #pragma unroll
    for (int i = 0; i < 4; i++) {
        mrow[i] = -1e30f; lrow[i] = 0.f;
        #pragma unroll
        for (int j = 0; j < 4; j++) O[i][j] = 0.f;
    }

    for (int k0 = 0; k0 < Sc; k0 += 64) {
        __syncthreads();
        for (int i = tid; i < 64*64; i += 256) {
            int rr = i >> 6, dd = i & 63;
            Ks[rr*65 + dd] = Kg[(k0 + rr)*64 + dd];
            Vs[rr*65 + dd] = Vg[(k0 + rr)*64 + dd];
        }
        __syncthreads();

        float sc[4][4];
        #pragma unroll
        for (int i = 0; i < 4; i++)
            #pragma unroll
            for (int j = 0; j < 4; j++) sc[i][j] = 0.f;

        #pragma unroll 8
        for (int d = 0; d < 64; d++) {
            float a[4], kv[4];
            #pragma unroll
            for (int i = 0; i < 4; i++) a[i]  = Qs[(ty*4+i)*65 + d];
            #pragma unroll
            for (int j = 0; j < 4; j++) kv[j] = Ks[(tx*4+j)*65 + d];
            #pragma unroll
            for (int i = 0; i < 4; i++)
                #pragma unroll
                for (int j = 0; j < 4; j++)
                    sc[i][j] = fmaf(a[i], kv[j], sc[i][j]);
        }

        float attv[4], kposf[4];
        #pragma unroll
        for (int j = 0; j < 4; j++) {
            attv[j]  = att[k0 + tx*4 + j];
            kposf[j] = (float)(k0 + tx*4 + j);
        }

        float mnew[4], corr[4];
        #pragma unroll
        for (int i = 0; i < 4; i++) {
            float mloc = -1e30f;
            #pragma unroll
            for (int j = 0; j < 4; j++) {
                float z = reachv[i] + attv[j] - fabsf(qposf[i] - kposf[j]) * inv_st;
                float sig = 1.0f / (1.0f + __expf(-z));
                float s = fmaf(sc[i][j], 0.125f, __logf(sig + 1e-8f));
                sc[i][j] = s;
                mloc = fmaxf(mloc, s);
            }
            mloc = fmaxf(mloc, __shfl_xor_sync(0xffffffffu, mloc, 1));
            mloc = fmaxf(mloc, __shfl_xor_sync(0xffffffffu, mloc, 2));
            mloc = fmaxf(mloc, __shfl_xor_sync(0xffffffffu, mloc, 4));
            mloc = fmaxf(mloc, __shfl_xor_sync(0xffffffffu, mloc, 8));
            mnew[i] = fmaxf(mrow[i], mloc);
            corr[i] = __expf(mrow[i] - mnew[i]);
            mrow[i] = mnew[i];
        }

        #pragma unroll
        for (int i = 0; i < 4; i++) {
            float ps = 0.f;
            #pragma unroll
            for (int j = 0; j < 4; j++) {
                float p = __expf(sc[i][j] - mnew[i]);
                Ps[(ty*4+i)*65 + tx*4 + j] = p;
                ps += p;
            }
            ps += __shfl_xor_sync(0xffffffffu, ps, 1);
            ps += __shfl_xor_sync(0xffffffffu, ps, 2);
            ps += __shfl_xor_sync(0xffffffffu, ps, 4);
            ps += __shfl_xor_sync(0xffffffffu, ps, 8);
            lrow[i] = lrow[i]*corr[i] + ps;
            #pragma unroll
            for (int j = 0; j < 4; j++) O[i][j] *= corr[i];
        }
        __syncthreads();

        #pragma unroll 8
        for (int k = 0; k < 64; k++) {
            float pi[4], vv[4];
            #pragma unroll
            for (int i = 0; i < 4; i++) pi[i] = Ps[(ty*4+i)*65 + k];
            #pragma unroll
            for (int j = 0; j < 4; j++) vv[j] = Vs[k*65 + tx*4 + j];
            #pragma unroll
            for (int i = 0; i < 4; i++)
                #pragma unroll
                for (int j = 0; j < 4; j++)
                    O[i][j] = fmaf(pi[i], vv[j], O[i][j]);
        }
    }

    #pragma unroll
    for (int i = 0; i < 4; i++) {
        float invl = 1.0f / lrow[i];
        float4 v;
        v.x = O[i][0]*invl; v.y = O[i][1]*invl;
        v.z = O[i][2]*invl; v.w = O[i][3]*invl;
        size_t off = ((size_t)(b*Sc + q0 + ty*4 + i))*Hc + h*HDc + tx*4;
        *reinterpret_cast<float4*>(&g_attn[off]) = v;
    }
}

// ---------------- residual + LayerNorm ----------------
__global__ __launch_bounds__(256) void ln_kernel(
    const float* __restrict__ hs, const float* __restrict__ gamma,
    const float* __restrict__ beta, float* __restrict__ out)
{
    int m = blockIdx.x;
    __shared__ float xs[Hc];
    __shared__ float red[8];
    __shared__ float stat[2];
    int tid = threadIdx.x;
    const float* hrow = hs + (size_t)m*Hc;
    const float* prow = g_proj + (size_t)m*Hc;

    float lsum = 0.f;
    for (int i = tid; i < Hc; i += 256) {
        float x = hrow[i] + prow[i];
        xs[i] = x;
        lsum += x;
    }
    #pragma unroll
    for (int o = 16; o > 0; o >>= 1) lsum += __shfl_xor_sync(0xffffffffu, lsum, o);
    if ((tid & 31) == 0) red[tid >> 5] = lsum;
    __syncthreads();
    if (tid == 0) {
        float s = 0.f;
        #pragma unroll
        for (int i = 0; i < 8; i++) s += red[i];
        stat[0] = s * (1.0f/(float)Hc);
    }
    __syncthreads();
    float mu = stat[0];

    float lvar = 0.f;
    for (int i = tid; i < Hc; i += 256) {
        float d = xs[i] - mu;
        lvar += d*d;
    }
    #pragma unroll
    for (int o = 16; o > 0; o >>= 1) lvar += __shfl_xor_sync(0xffffffffu, lvar, o);
    if ((tid & 31) == 0) red[tid >> 5] = lvar;
    __syncthreads();
    if (tid == 0) {
        float s = 0.f;
        #pragma unroll
        for (int i = 0; i < 8; i++) s += red[i];
        stat[1] = rsqrtf(s * (1.0f/(float)Hc) + 1e-5f);
    }
    __syncthreads();
    float rstd = stat[1];

    float* orow = out + (size_t)m*Hc;
    for (int i = tid; i < Hc; i += 256)
        orow[i] = (xs[i] - mu) * rstd * gamma[i] + beta[i];
}

// ---------------- launch ----------------
extern "C" void kernel_launch(void* const* d_in, const int* in_sizes, int n_in,
                              void* d_out, int out_size) {
    (void)in_sizes; (void)n_in; (void)out_size;
    const float* hs   = (const float*)d_in[0];
    const float* imp  = (const float*)d_in[1];
    const float* wq   = (const float*)d_in[2];
    const float* bq   = (const float*)d_in[3];
    const float* wk   = (const float*)d_in[4];
    const float* bk   = (const float*)d_in[5];
    const float* wv   = (const float*)d_in[6];
    const float* bv   = (const float*)d_in[7];
    const float* wo   = (const float*)d_in[8];
    const float* bo   = (const float*)d_in[9];
    const float* rw1  = (const float*)d_in[10];
    const float* rb1  = (const float*)d_in[11];
    const float* rw2  = (const float*)d_in[12];
    const float* rb2  = (const float*)d_in[13];
    const float* aw1  = (const float*)d_in[14];
    const float* ab1  = (const float*)d_in[15];
    const float* aw2  = (const float*)d_in[16];
    const float* ab2  = (const float*)d_in[17];
    const float* logt = (const float*)d_in[18];
    const float* lng  = (const float*)d_in[19];
    const float* lnb  = (const float*)d_in[20];
    float* out = (float*)d_out;

    cudaFuncSetAttribute(flash_kernel,
                         cudaFuncAttributeMaxDynamicSharedMemorySize,
                         FL_SMEM_FLOATS * (int)sizeof(float));

    mask_mlp_kernel<<<(Bc*Sc + 255)/256, 256>>>(imp, rw1, rb1, rw2, rb2,
                                                aw1, ab1, aw2, ab2);

    dim3 gg(Hc/128, Mtot/128);   // (8, 32)
    gemm_kernel<0><<<gg, 256>>>(hs, wq, bq);
    gemm_kernel<1><<<gg, 256>>>(hs, wk, bk);
    gemm_kernel<2><<<gg, 256>>>(hs, wv, bv);

    flash_kernel<<<dim3(Sc/64, 1, Bc*NHc), 256,
                   FL_SMEM_FLOATS * (int)sizeof(float)>>>(logt);

    gemm_kernel<3><<<gg, 256>>>(hs, wo, bo);

    ln_kernel<<<Mtot, 256>>>(hs, lng, lnb, out);
}

// round 2
// speedup vs baseline: 3.1214x; 3.1214x over previous
#include <cuda_runtime.h>
#include <math.h>

// ---------------- problem constants ----------------
#define Bc   2
#define Sc   2048
#define Hc   1024
#define NHc  16
#define HDc  64
#define MLPc 32
#define Mtot (Bc*Sc)   // 4096

// ---------------- scratch ----------------
__device__ float g_Q[(size_t)Bc*NHc*Sc*HDc];
__device__ float g_K[(size_t)Bc*NHc*Sc*HDc];
__device__ float g_V[(size_t)Bc*NHc*Sc*HDc];
__device__ float g_reach[Bc*NHc*Sc];
__device__ float g_attract[Bc*NHc*Sc];
__device__ float g_attn[(size_t)Mtot*Hc];
__device__ float g_proj[(size_t)Mtot*Hc];

// ---------------- tf32 helpers ----------------
__device__ __forceinline__ unsigned f2tf(float x){
    unsigned u; asm("cvt.rna.tf32.f32 %0, %1;" : "=r"(u) : "f"(x)); return u;
}
__device__ __forceinline__ float tfv(float x){ return __uint_as_float(f2tf(x)); }

__device__ __forceinline__ void mma8(float* c,
    unsigned a0, unsigned a1, unsigned a2, unsigned a3,
    unsigned b0, unsigned b1)
{
    asm volatile(
      "mma.sync.aligned.m16n8k8.row.col.f32.tf32.tf32.f32 "
      "{%0,%1,%2,%3}, {%4,%5,%6,%7}, {%8,%9}, {%0,%1,%2,%3};"
      : "+f"(c[0]), "+f"(c[1]), "+f"(c[2]), "+f"(c[3])
      : "r"(a0), "r"(a1), "r"(a2), "r"(a3), "r"(b0), "r"(b1));
}

// ---------------- mask MLPs ----------------
__global__ void mask_mlp_kernel(const float* __restrict__ imp,
    const float* __restrict__ rw1, const float* __restrict__ rb1,
    const float* __restrict__ rw2, const float* __restrict__ rb2,
    const float* __restrict__ aw1, const float* __restrict__ ab1,
    const float* __restrict__ aw2, const float* __restrict__ ab2)
{
    int idx = blockIdx.x * blockDim.x + threadIdx.x;
    if (idx >= Bc*Sc) return;
    float x = imp[idx];
    float hr[MLPc], ha[MLPc];
    const float kInvSqrt2 = 0.70710678118654752440f;
    #pragma unroll
    for (int j = 0; j < MLPc; j++) {
        float t = fmaf(x, rw1[j], rb1[j]);
        hr[j] = 0.5f * t * (1.0f + erff(t * kInvSqrt2));
        float u = fmaf(x, aw1[j], ab1[j]);
        ha[j] = 0.5f * u * (1.0f + erff(u * kInvSqrt2));
    }
    int b = idx / Sc, s = idx - b * Sc;
    #pragma unroll
    for (int h = 0; h < NHc; h++) {
        float rs = rb2[h], as = ab2[h];
        #pragma unroll
        for (int j = 0; j < MLPc; j++) {
            rs = fmaf(hr[j], rw2[j*NHc + h], rs);
            as = fmaf(ha[j], aw2[j*NHc + h], as);
        }
        g_reach[(b*NHc + h)*Sc + s]   = rs;
        g_attract[(b*NHc + h)*Sc + s] = as;
    }
}

// ---------------- tensor-core GEMM (tf32): C = A(4096x1024) @ W(1024x1024) + b ----
// 128x128 CTA tile, 256 thr (8 warps, 4x2), warp tile 32x64, K-chunk 32, dbl-buffer.
#define GA_STR 36
#define GW_STR 136
#define GASZ (128*GA_STR)
#define GWSZ (32*GW_STR)
#define G_SMEMF (2*(GASZ+GWSZ))

template<int OUTSEL>
__global__ __launch_bounds__(256) void gemm_tc(
    const float* __restrict__ Ain, const float* __restrict__ W,
    const float* __restrict__ bias)
{
    extern __shared__ float sm[];
    float* Abuf[2] = { sm, sm + GASZ };
    float* Wbuf[2] = { sm + 2*GASZ, sm + 2*GASZ + GWSZ };

    const float* A = (OUTSEL == 3) ? (const float*)g_attn : Ain;
    int m0 = blockIdx.y * 128, n0 = blockIdx.x * 128;
    int tid = threadIdx.x;
    int wid = tid >> 5, lane = tid & 31;
    int mw = wid & 3, nw = wid >> 2;
    int g = lane >> 2, tq = lane & 3;
    int ar = tid >> 3, ac = (tid & 7) * 4;

    float C[2][8][4];
    #pragma unroll
    for (int mt = 0; mt < 2; mt++)
        #pragma unroll
        for (int nt = 0; nt < 8; nt++)
            #pragma unroll
            for (int q = 0; q < 4; q++) C[mt][nt][q] = 0.f;

    float4 asg[4], wsg[4];
    // prologue: load kt=0
    #pragma unroll
    for (int l = 0; l < 4; l++) {
        asg[l] = *(const float4*)&A[(size_t)(m0 + ar + 32*l)*Hc + ac];
        int idx = tid + 256*l; int wr = idx >> 5, wc = (idx & 31) * 4;
        wsg[l] = *(const float4*)&W[(size_t)wr*Hc + n0 + wc];
    }
    #pragma unroll
    for (int l = 0; l < 4; l++) {
        float4 t; t.x=tfv(asg[l].x); t.y=tfv(asg[l].y); t.z=tfv(asg[l].z); t.w=tfv(asg[l].w);
        *(float4*)&Abuf[0][(ar + 32*l)*GA_STR + ac] = t;
        int idx = tid + 256*l; int wr = idx >> 5, wc = (idx & 31) * 4;
        float4 u; u.x=tfv(wsg[l].x); u.y=tfv(wsg[l].y); u.z=tfv(wsg[l].z); u.w=tfv(wsg[l].w);
        *(float4*)&Wbuf[0][wr*GW_STR + wc] = u;
    }
    __syncthreads();

    for (int kt = 0; kt < 32; kt++) {
        float* Asc = Abuf[kt & 1];
        float* Wsc = Wbuf[kt & 1];
        if (kt < 31) {
            #pragma unroll
            for (int l = 0; l < 4; l++) {
                asg[l] = *(const float4*)&A[(size_t)(m0 + ar + 32*l)*Hc + (kt+1)*32 + ac];
                int idx = tid + 256*l; int wr = idx >> 5, wc = (idx & 31) * 4;
                wsg[l] = *(const float4*)&W[(size_t)((kt+1)*32 + wr)*Hc + n0 + wc];
            }
        }
        #pragma unroll
        for (int ks = 0; ks < 4; ks++) {
            unsigned a[2][4];
            #pragma unroll
            for (int mt = 0; mt < 2; mt++) {
                int row = mw*32 + mt*16 + g;
                a[mt][0] = __float_as_uint(Asc[row*GA_STR + ks*8 + tq]);
                a[mt][1] = __float_as_uint(Asc[(row+8)*GA_STR + ks*8 + tq]);
                a[mt][2] = __float_as_uint(Asc[row*GA_STR + ks*8 + tq + 4]);
                a[mt][3] = __float_as_uint(Asc[(row+8)*GA_STR + ks*8 + tq + 4]);
            }
            #pragma unroll
            for (int nt = 0; nt < 8; nt++) {
                int col = nw*64 + nt*8 + g;
                unsigned b0 = __float_as_uint(Wsc[(ks*8+tq)*GW_STR + col]);
                unsigned b1 = __float_as_uint(Wsc[(ks*8+tq+4)*GW_STR + col]);
                mma8(C[0][nt], a[0][0], a[0][1], a[0][2], a[0][3], b0, b1);
                mma8(C[1][nt], a[1][0], a[1][1], a[1][2], a[1][3], b0, b1);
            }
        }
        if (kt < 31) {
            float* Asn = Abuf[(kt+1) & 1];
            float* Wsn = Wbuf[(kt+1) & 1];
            #pragma unroll
            for (int l = 0; l < 4; l++) {
                float4 t; t.x=tfv(asg[l].x); t.y=tfv(asg[l].y); t.z=tfv(asg[l].z); t.w=tfv(asg[l].w);
                *(float4*)&Asn[(ar + 32*l)*GA_STR + ac] = t;
                int idx = tid + 256*l; int wr = idx >> 5, wc = (idx & 31) * 4;
                float4 u; u.x=tfv(wsg[l].x); u.y=tfv(wsg[l].y); u.z=tfv(wsg[l].z); u.w=tfv(wsg[l].w);
                *(float4*)&Wsn[wr*GW_STR + wc] = u;
            }
            __syncthreads();
        }
    }

    // epilogue
    #pragma unroll
    for (int mt = 0; mt < 2; mt++) {
        int r0 = m0 + mw*32 + mt*16 + g;
        #pragma unroll
        for (int nt = 0; nt < 8; nt++) {
            int col = n0 + nw*64 + nt*8 + 2*tq;
            float2 bv = *(const float2*)&bias[col];
            float2 v0 = make_float2(C[mt][nt][0] + bv.x, C[mt][nt][1] + bv.y);
            float2 v1 = make_float2(C[mt][nt][2] + bv.x, C[mt][nt][3] + bv.y);
            if (OUTSEL < 3) {
                float* outp = (OUTSEL == 0) ? g_Q : (OUTSEL == 1) ? g_K : g_V;
                int hh = col >> 6, dd = col & 63;
                int bb = r0 >> 11, ss0 = r0 & 2047;
                *(float2*)&outp[(((size_t)bb*NHc + hh)*Sc + ss0    )*HDc + dd] = v0;
                *(float2*)&outp[(((size_t)bb*NHc + hh)*Sc + ss0 + 8)*HDc + dd] = v1;
            } else {
                *(float2*)&g_proj[(size_t)r0*Hc + col]     = v0;
                *(float2*)&g_proj[(size_t)(r0+8)*Hc + col] = v1;
            }
        }
    }
}

// ---------------- tensor-core flash attention (tf32) ----------------
// grid (32, 32); 128 thr (4 warps); CTA tile 64q x 64k; warp = 16 q-rows.
#define FQ_STR 68
#define FV_STR 72
#define FLK (64*FQ_STR)
#define FLV (2*64*FQ_STR)
#define FLP (FLV + 64*FV_STR)
#define FLA (FLP + 4*16*FQ_STR)
#define FL_SMEMF (FLA + 64)

__global__ __launch_bounds__(128) void flash_tc(const float* __restrict__ log_temp)
{
    extern __shared__ float sm[];
    float* Qs  = sm;
    float* Ks  = sm + FLK;
    float* Vs  = sm + FLV;
    float* Att = sm + FLA;
    int tid = threadIdx.x, wid = tid >> 5, lane = tid & 31;
    float* Ps = sm + FLP + wid * 16 * FQ_STR;   // per-warp
    int g = lane >> 2, tq = lane & 3;
    int bh = blockIdx.y, b = bh >> 4, h = bh & 15;
    int q0 = blockIdx.x * 64;

    const float* Qg = g_Q + ((size_t)bh*Sc + q0) * HDc;
    const float* Kg = g_K + (size_t)bh*Sc*HDc;
    const float* Vg = g_V + (size_t)bh*Sc*HDc;

    #pragma unroll
    for (int l = 0; l < 8; l++) {
        int idx = tid + 128*l; int r = idx >> 4, c = (idx & 15) * 4;
        float4 v = *(const float4*)&Qg[r*HDc + c];
        float4 t; t.x=tfv(v.x); t.y=tfv(v.y); t.z=tfv(v.z); t.w=tfv(v.w);
        *(float4*)&Qs[r*FQ_STR + c] = t;
    }
    int rb = wid*16 + g;
    float reach_lo = g_reach[bh*Sc + q0 + rb];
    float reach_hi = g_reach[bh*Sc + q0 + rb + 8];
    float ip_lo = (float)(q0 + rb), ip_hi = ip_lo + 8.0f;
    float temp = __expf(log_temp[h]) + 1.0f;
    float inv_st = __fdividef(1.0f, (float)Sc * temp);

    float m_lo = -1e30f, m_hi = -1e30f, l_lo = 0.f, l_hi = 0.f;
    float O[8][4];
    #pragma unroll
    for (int nt = 0; nt < 8; nt++)
        #pragma unroll
        for (int q = 0; q < 4; q++) O[nt][q] = 0.f;

    for (int kt = 0; kt < 32; kt++) {
        int k0 = kt * 64;
        __syncthreads();
        #pragma unroll
        for (int l = 0; l < 8; l++) {
            int idx = tid + 128*l; int r = idx >> 4, c = (idx & 15) * 4;
            float4 kv = *(const float4*)&Kg[(size_t)(k0 + r)*HDc + c];
            float4 tk; tk.x=tfv(kv.x); tk.y=tfv(kv.y); tk.z=tfv(kv.z); tk.w=tfv(kv.w);
            *(float4*)&Ks[r*FQ_STR + c] = tk;
            float4 vv = *(const float4*)&Vg[(size_t)(k0 + r)*HDc + c];
            float4 tv; tv.x=tfv(vv.x); tv.y=tfv(vv.y); tv.z=tfv(vv.z); tv.w=tfv(vv.w);
            *(float4*)&Vs[r*FV_STR + c] = tv;
        }
        if (tid < 64) Att[tid] = g_attract[bh*Sc + k0 + tid];
        __syncthreads();

        // S = Q K^T
        float C[8][4];
        #pragma unroll
        for (int nt = 0; nt < 8; nt++)
            #pragma unroll
            for (int q = 0; q < 4; q++) C[nt][q] = 0.f;
        #pragma unroll
        for (int ks = 0; ks < 8; ks++) {
            unsigned a0 = __float_as_uint(Qs[rb*FQ_STR + ks*8 + tq]);
            unsigned a1 = __float_as_uint(Qs[(rb+8)*FQ_STR + ks*8 + tq]);
            unsigned a2 = __float_as_uint(Qs[rb*FQ_STR + ks*8 + tq + 4]);
            unsigned a3 = __float_as_uint(Qs[(rb+8)*FQ_STR + ks*8 + tq + 4]);
            #pragma unroll
            for (int nt = 0; nt < 8; nt++) {
                unsigned b0 = __float_as_uint(Ks[(nt*8+g)*FQ_STR + ks*8 + tq]);
                unsigned b1 = __float_as_uint(Ks[(nt*8+g)*FQ_STR + ks*8 + tq + 4]);
                mma8(C[nt], a0, a1, a2, a3, b0, b1);
            }
        }

        // pass1: scale + row max (m = max(s) bounds s + log(sig) since log(sig+1e-8) <= ~0)
        float ml = -1e30f, mh = -1e30f;
        #pragma unroll
        for (int nt = 0; nt < 8; nt++) {
            #pragma unroll
            for (int q = 0; q < 4; q++) C[nt][q] *= 0.125f;
            ml = fmaxf(ml, fmaxf(C[nt][0], C[nt][1]));
            mh = fmaxf(mh, fmaxf(C[nt][2], C[nt][3]));
        }
        ml = fmaxf(ml, __shfl_xor_sync(0xffffffffu, ml, 1));
        ml = fmaxf(ml, __shfl_xor_sync(0xffffffffu, ml, 2));
        mh = fmaxf(mh, __shfl_xor_sync(0xffffffffu, mh, 1));
        mh = fmaxf(mh, __shfl_xor_sync(0xffffffffu, mh, 2));
        float mn_lo = fmaxf(m_lo, ml), mn_hi = fmaxf(m_hi, mh);
        float corr_lo = __expf(m_lo - mn_lo), corr_hi = __expf(m_hi - mn_hi);
        m_lo = mn_lo; m_hi = mn_hi;

        // pass2: p = (sigmoid(z)+1e-8) * exp(s - m)   [log folded out]
        float rs_lo = 0.f, rs_hi = 0.f;
        #pragma unroll
        for (int nt = 0; nt < 8; nt++) {
            int jc = nt*8 + 2*tq;
            float att0 = Att[jc], att1 = Att[jc+1];
            float j0 = (float)(k0 + jc), j1 = j0 + 1.0f;
            float z00 = reach_lo + att0 - fabsf(ip_lo - j0)*inv_st;
            float z01 = reach_lo + att1 - fabsf(ip_lo - j1)*inv_st;
            float z10 = reach_hi + att0 - fabsf(ip_hi - j0)*inv_st;
            float z11 = reach_hi + att1 - fabsf(ip_hi - j1)*inv_st;
            float w00 = __fdividef(1.f, 1.f + __expf(-z00)) + 1e-8f;
            float w01 = __fdividef(1.f, 1.f + __expf(-z01)) + 1e-8f;
            float w10 = __fdividef(1.f, 1.f + __expf(-z10)) + 1e-8f;
            float w11 = __fdividef(1.f, 1.f + __expf(-z11)) + 1e-8f;
            float p00 = w00 * __expf(C[nt][0] - m_lo);
            float p01 = w01 * __expf(C[nt][1] - m_lo);
            float p10 = w10 * __expf(C[nt][2] - m_hi);
            float p11 = w11 * __expf(C[nt][3] - m_hi);
            Ps[g*FQ_STR + jc]       = tfv(p00);
            Ps[g*FQ_STR + jc + 1]   = tfv(p01);
            Ps[(g+8)*FQ_STR + jc]   = tfv(p10);
            Ps[(g+8)*FQ_STR + jc+1] = tfv(p11);
            rs_lo += p00 + p01; rs_hi += p10 + p11;
        }
        rs_lo += __shfl_xor_sync(0xffffffffu, rs_lo, 1);
        rs_lo += __shfl_xor_sync(0xffffffffu, rs_lo, 2);
        rs_hi += __shfl_xor_sync(0xffffffffu, rs_hi, 1);
        rs_hi += __shfl_xor_sync(0xffffffffu, rs_hi, 2);
        l_lo = l_lo*corr_lo + rs_lo;
        l_hi = l_hi*corr_hi + rs_hi;
        #pragma unroll
        for (int nt = 0; nt < 8; nt++) {
            O[nt][0] *= corr_lo; O[nt][1] *= corr_lo;
            O[nt][2] *= corr_hi; O[nt][3] *= corr_hi;
        }
        __syncwarp();

        // O += P V
        #pragma unroll
        for (int ks = 0; ks < 8; ks++) {
            unsigned a0 = __float_as_uint(Ps[g*FQ_STR + ks*8 + tq]);
            unsigned a1 = __float_as_uint(Ps[(g+8)*FQ_STR + ks*8 + tq]);
            unsigned a2 = __float_as_uint(Ps[g*FQ_STR + ks*8 + tq + 4]);
            unsigned a3 = __float_as_uint(Ps[(g+8)*FQ_STR + ks*8 + tq + 4]);
            #pragma unroll
            for (int nt = 0; nt < 8; nt++) {
                unsigned b0 = __float_as_uint(Vs[(ks*8+tq)*FV_STR + nt*8 + g]);
                unsigned b1 = __float_as_uint(Vs[(ks*8+tq+4)*FV_STR + nt*8 + g]);
                mma8(O[nt], a0, a1, a2, a3, b0, b1);
            }
        }
    }

    float il = __fdividef(1.f, l_lo), ih = __fdividef(1.f, l_hi);
    int r_lo = q0 + rb;
    #pragma unroll
    for (int nt = 0; nt < 8; nt++) {
        int col = h*HDc + nt*8 + 2*tq;
        float2 v0 = make_float2(O[nt][0]*il, O[nt][1]*il);
        float2 v1 = make_float2(O[nt][2]*ih, O[nt][3]*ih);
        *(float2*)&g_attn[(size_t)(b*Sc + r_lo    )*Hc + col] = v0;
        *(float2*)&g_attn[(size_t)(b*Sc + r_lo + 8)*Hc + col] = v1;
    }
}

// ---------------- residual + LayerNorm ----------------
__global__ __launch_bounds__(256) void ln_kernel(
    const float* __restrict__ hs, const float* __restrict__ gamma,
    const float* __restrict__ beta, float* __restrict__ out)
{
    int m = blockIdx.x;
    __shared__ float xs[Hc];
    __shared__ float red[8];
    __shared__ float stat[2];
    int tid = threadIdx.x;
    const float* hrow = hs + (size_t)m*Hc;
    const float* prow = g_proj + (size_t)m*Hc;

    float lsum = 0.f;
    for (int i = tid; i < Hc; i += 256) {
        float x = hrow[i] + prow[i];
        xs[i] = x;
        lsum += x;
    }
    #pragma unroll
    for (int o = 16; o > 0; o >>= 1) lsum += __shfl_xor_sync(0xffffffffu, lsum, o);
    if ((tid & 31) == 0) red[tid >> 5] = lsum;
    __syncthreads();
    if (tid == 0) {
        float s = 0.f;
        #pragma unroll
        for (int i = 0; i < 8; i++) s += red[i];
        stat[0] = s * (1.0f/(float)Hc);
    }
    __syncthreads();
    float mu = stat[0];

    float lvar = 0.f;
    for (int i = tid; i < Hc; i += 256) {
        float d = xs[i] - mu;
        lvar += d*d;
    }
    #pragma unroll
    for (int o = 16; o > 0; o >>= 1) lvar += __shfl_xor_sync(0xffffffffu, lvar, o);
    if ((tid & 31) == 0) red[tid >> 5] = lvar;
    __syncthreads();
    if (tid == 0) {
        float s = 0.f;
        #pragma unroll
        for (int i = 0; i < 8; i++) s += red[i];
        stat[1] = rsqrtf(s * (1.0f/(float)Hc) + 1e-5f);
    }
    __syncthreads();
    float rstd = stat[1];

    float* orow = out + (size_t)m*Hc;
    for (int i = tid; i < Hc; i += 256)
        orow[i] = (xs[i] - mu) * rstd * gamma[i] + beta[i];
}

// ---------------- launch ----------------
extern "C" void kernel_launch(void* const* d_in, const int* in_sizes, int n_in,
                              void* d_out, int out_size) {
    (void)in_sizes; (void)n_in; (void)out_size;
    const float* hs   = (const float*)d_in[0];
    const float* imp  = (const float*)d_in[1];
    const float* wq   = (const float*)d_in[2];
    const float* bq   = (const float*)d_in[3];
    const float* wk   = (const float*)d_in[4];
    const float* bk   = (const float*)d_in[5];
    const float* wv   = (const float*)d_in[6];
    const float* bv   = (const float*)d_in[7];
    const float* wo   = (const float*)d_in[8];
    const float* bo   = (const float*)d_in[9];
    const float* rw1  = (const float*)d_in[10];
    const float* rb1  = (const float*)d_in[11];
    const float* rw2  = (const float*)d_in[12];
    const float* rb2  = (const float*)d_in[13];
    const float* aw1  = (const float*)d_in[14];
    const float* ab1  = (const float*)d_in[15];
    const float* aw2  = (const float*)d_in[16];
    const float* ab2  = (const float*)d_in[17];
    const float* logt = (const float*)d_in[18];
    const float* lng  = (const float*)d_in[19];
    const float* lnb  = (const float*)d_in[20];
    float* out = (float*)d_out;

    const int gsmem = G_SMEMF * (int)sizeof(float);
    const int fsmem = FL_SMEMF * (int)sizeof(float);
    cudaFuncSetAttribute(gemm_tc<0>, cudaFuncAttributeMaxDynamicSharedMemorySize, gsmem);
    cudaFuncSetAttribute(gemm_tc<1>, cudaFuncAttributeMaxDynamicSharedMemorySize, gsmem);
    cudaFuncSetAttribute(gemm_tc<2>, cudaFuncAttributeMaxDynamicSharedMemorySize, gsmem);
    cudaFuncSetAttribute(gemm_tc<3>, cudaFuncAttributeMaxDynamicSharedMemorySize, gsmem);
    cudaFuncSetAttribute(flash_tc,   cudaFuncAttributeMaxDynamicSharedMemorySize, fsmem);

    mask_mlp_kernel<<<(Bc*Sc + 255)/256, 256>>>(imp, rw1, rb1, rw2, rb2,
                                                aw1, ab1, aw2, ab2);

    dim3 gg(Hc/128, Mtot/128);   // (8, 32)
    gemm_tc<0><<<gg, 256, gsmem>>>(hs, wq, bq);
    gemm_tc<1><<<gg, 256, gsmem>>>(hs, wk, bk);
    gemm_tc<2><<<gg, 256, gsmem>>>(hs, wv, bv);

    flash_tc<<<dim3(Sc/64, Bc*NHc), 128, fsmem>>>(logt);

    gemm_tc<3><<<gg, 256, gsmem>>>(hs, wo, bo);

    ln_kernel<<<Mtot, 256>>>(hs, lng, lnb, out);
}

// round 3
// speedup vs baseline: 3.6878x; 1.1815x over previous
#include <cuda_runtime.h>
#include <math.h>
#include <stdint.h>

// ---------------- problem constants ----------------
#define Bc   2
#define Sc   2048
#define Hc   1024
#define NHc  16
#define HDc  64
#define MLPc 32
#define Mtot (Bc*Sc)   // 4096

// ---------------- scratch ----------------
__device__ float g_Q[(size_t)Bc*NHc*Sc*HDc];
__device__ float g_K[(size_t)Bc*NHc*Sc*HDc];
__device__ float g_V[(size_t)Bc*NHc*Sc*HDc];
__device__ float g_reach[Bc*NHc*Sc];
__device__ float g_attract[Bc*NHc*Sc];
__device__ float g_attn[(size_t)Mtot*Hc];
__device__ float g_proj[(size_t)Mtot*Hc];

// ---------------- mma + cp.async helpers ----------------
__device__ __forceinline__ void mma8(float* c,
    unsigned a0, unsigned a1, unsigned a2, unsigned a3,
    unsigned b0, unsigned b1)
{
    asm volatile(
      "mma.sync.aligned.m16n8k8.row.col.f32.tf32.tf32.f32 "
      "{%0,%1,%2,%3}, {%4,%5,%6,%7}, {%8,%9}, {%0,%1,%2,%3};"
      : "+f"(c[0]), "+f"(c[1]), "+f"(c[2]), "+f"(c[3])
      : "r"(a0), "r"(a1), "r"(a2), "r"(a3), "r"(b0), "r"(b1));
}

__device__ __forceinline__ void cpa16(uint32_t s, const void* g){
    asm volatile("cp.async.cg.shared.global [%0], [%1], 16;\n" :: "r"(s), "l"(g));
}
#define CP_COMMIT()  asm volatile("cp.async.commit_group;\n" ::: "memory")
#define CP_WAIT(N)   asm volatile("cp.async.wait_group %0;\n" :: "n"(N) : "memory")

__device__ __forceinline__ uint32_t smem_u32(const void* p){
    uint32_t a;
    asm("{ .reg .u64 t; cvta.to.shared.u64 t, %1; cvt.u32.u64 %0, t; }" : "=r"(a) : "l"(p));
    return a;
}

// ---------------- mask MLPs ----------------
__global__ void mask_mlp_kernel(const float* __restrict__ imp,
    const float* __restrict__ rw1, const float* __restrict__ rb1,
    const float* __restrict__ rw2, const float* __restrict__ rb2,
    const float* __restrict__ aw1, const float* __restrict__ ab1,
    const float* __restrict__ aw2, const float* __restrict__ ab2)
{
    int idx = blockIdx.x * blockDim.x + threadIdx.x;
    if (idx >= Bc*Sc) return;
    float x = imp[idx];
    float hr[MLPc], ha[MLPc];
    const float kInvSqrt2 = 0.70710678118654752440f;
    #pragma unroll
    for (int j = 0; j < MLPc; j++) {
        float t = fmaf(x, rw1[j], rb1[j]);
        hr[j] = 0.5f * t * (1.0f + erff(t * kInvSqrt2));
        float u = fmaf(x, aw1[j], ab1[j]);
        ha[j] = 0.5f * u * (1.0f + erff(u * kInvSqrt2));
    }
    int b = idx / Sc, s = idx - b * Sc;
    #pragma unroll
    for (int h = 0; h < NHc; h++) {
        float rs = rb2[h], as = ab2[h];
        #pragma unroll
        for (int j = 0; j < MLPc; j++) {
            rs = fmaf(hr[j], rw2[j*NHc + h], rs);
            as = fmaf(ha[j], aw2[j*NHc + h], as);
        }
        g_reach[(b*NHc + h)*Sc + s]   = rs;
        g_attract[(b*NHc + h)*Sc + s] = as;
    }
}

// ---------------- tensor-core GEMM, cp.async 4-stage pipeline ----------------
// 128x128 CTA tile, 256 thr (8 warps 4x2, warp tile 32x64), K-chunk 16.
// MODE 0: fused QKV (grid.x 24, wsel by block), transposed store.
// MODE 1: O-projection (A = g_attn, store g_proj).
#define AST 20
#define WST 136
#define ASZ (128*AST)       // 2560 floats
#define WSZ (16*WST)        // 2176 floats
#define STG (ASZ+WSZ)       // 4736 floats / stage
#define G_SMEMF (4*STG)     // 18944 floats = 75776 B

template<int MODE>
__global__ __launch_bounds__(256, 2) void gemm_tc(
    const float* __restrict__ Ain,
    const float* __restrict__ W0, const float* __restrict__ W1, const float* __restrict__ W2,
    const float* __restrict__ b0p, const float* __restrict__ b1p, const float* __restrict__ b2p)
{
    extern __shared__ float sm[];
    uint32_t smb = smem_u32(sm);

    const float* A = (MODE == 1) ? (const float*)g_attn : Ain;
    int wsel = (MODE == 0) ? (blockIdx.x >> 3) : 0;
    const float* W    = (wsel == 0) ? W0 : (wsel == 1) ? W1 : W2;
    const float* bias = (wsel == 0) ? b0p : (wsel == 1) ? b1p : b2p;
    float* outp = (MODE == 1) ? g_proj : ((wsel == 0) ? g_Q : (wsel == 1) ? g_K : g_V);
    int n0 = (MODE == 0) ? ((blockIdx.x & 7) * 128) : (blockIdx.x * 128);
    int m0 = blockIdx.y * 128;

    int tid = threadIdx.x;
    int wid = tid >> 5, lane = tid & 31;
    int mw = wid & 3, nw = wid >> 2;
    int g = lane >> 2, tq = lane & 3;

    // per-thread copy coordinates
    int ac0 = tid, ac1 = tid + 256;              // A chunks
    int arow0 = ac0 >> 2, ak0 = (ac0 & 3) * 4;
    int arow1 = ac1 >> 2, ak1 = (ac1 & 3) * 4;
    int wr0 = ac0 >> 5, wc0 = (ac0 & 31) * 4;    // W chunks
    int wr1 = ac1 >> 5, wc1 = (ac1 & 31) * 4;

    float C[2][8][4];
    #pragma unroll
    for (int mt = 0; mt < 2; mt++)
        #pragma unroll
        for (int nt = 0; nt < 8; nt++)
            #pragma unroll
            for (int q = 0; q < 4; q++) C[mt][nt][q] = 0.f;

    // prologue: issue stages 0..2
    #pragma unroll
    for (int s = 0; s < 3; s++) {
        int k0 = s * 16;
        uint32_t base = smb + (uint32_t)(s * STG) * 4u;
        cpa16(base + (arow0*AST + ak0)*4, &A[(size_t)(m0 + arow0)*Hc + k0 + ak0]);
        cpa16(base + (arow1*AST + ak1)*4, &A[(size_t)(m0 + arow1)*Hc + k0 + ak1]);
        cpa16(base + (ASZ + wr0*WST + wc0)*4, &W[(size_t)(k0 + wr0)*Hc + n0 + wc0]);
        cpa16(base + (ASZ + wr1*WST + wc1)*4, &W[(size_t)(k0 + wr1)*Hc + n0 + wc1]);
        CP_COMMIT();
    }

    for (int kt = 0; kt < 64; kt++) {
        CP_WAIT(2);
        __syncthreads();
        if (kt + 3 < 64) {
            int k0 = (kt + 3) * 16;
            uint32_t base = smb + (uint32_t)(((kt + 3) & 3) * STG) * 4u;
            cpa16(base + (arow0*AST + ak0)*4, &A[(size_t)(m0 + arow0)*Hc + k0 + ak0]);
            cpa16(base + (arow1*AST + ak1)*4, &A[(size_t)(m0 + arow1)*Hc + k0 + ak1]);
            cpa16(base + (ASZ + wr0*WST + wc0)*4, &W[(size_t)(k0 + wr0)*Hc + n0 + wc0]);
            cpa16(base + (ASZ + wr1*WST + wc1)*4, &W[(size_t)(k0 + wr1)*Hc + n0 + wc1]);
        }
        CP_COMMIT();

        const float* Asc = sm + (kt & 3) * STG;
        const float* Wsc = Asc + ASZ;
        #pragma unroll
        for (int ks = 0; ks < 2; ks++) {
            unsigned a[2][4];
            #pragma unroll
            for (int mt = 0; mt < 2; mt++) {
                int row = mw*32 + mt*16 + g;
                a[mt][0] = __float_as_uint(Asc[row*AST + ks*8 + tq]);
                a[mt][1] = __float_as_uint(Asc[(row+8)*AST + ks*8 + tq]);
                a[mt][2] = __float_as_uint(Asc[row*AST + ks*8 + tq + 4]);
                a[mt][3] = __float_as_uint(Asc[(row+8)*AST + ks*8 + tq + 4]);
            }
            #pragma unroll
            for (int nt = 0; nt < 8; nt++) {
                int col = nw*64 + nt*8 + g;
                unsigned bb0 = __float_as_uint(Wsc[(ks*8+tq)*WST + col]);
                unsigned bb1 = __float_as_uint(Wsc[(ks*8+tq+4)*WST + col]);
                mma8(C[0][nt], a[0][0], a[0][1], a[0][2], a[0][3], bb0, bb1);
                mma8(C[1][nt], a[1][0], a[1][1], a[1][2], a[1][3], bb0, bb1);
            }
        }
    }

    // epilogue
    #pragma unroll
    for (int mt = 0; mt < 2; mt++) {
        int r0 = m0 + mw*32 + mt*16 + g;
        #pragma unroll
        for (int nt = 0; nt < 8; nt++) {
            int col = n0 + nw*64 + nt*8 + 2*tq;
            float2 bv = *(const float2*)&bias[col];
            float2 v0 = make_float2(C[mt][nt][0] + bv.x, C[mt][nt][1] + bv.y);
            float2 v1 = make_float2(C[mt][nt][2] + bv.x, C[mt][nt][3] + bv.y);
            if (MODE == 0) {
                int hh = col >> 6, dd = col & 63;
                int bb = r0 >> 11, ss0 = r0 & 2047;
                *(float2*)&outp[(((size_t)bb*NHc + hh)*Sc + ss0    )*HDc + dd] = v0;
                *(float2*)&outp[(((size_t)bb*NHc + hh)*Sc + ss0 + 8)*HDc + dd] = v1;
            } else {
                *(float2*)&outp[(size_t)r0*Hc + col]     = v0;
                *(float2*)&outp[(size_t)(r0+8)*Hc + col] = v1;
            }
        }
    }
}

// ---------------- flash attention, cp.async double-buffered K/V ----------------
// grid (32, 32); 128 thr (4 warps); 64q x 64k tiles; warp = 16 q rows.
#define FQ_STR 68
#define FV_STR 72
#define FKSZ (64*FQ_STR)           // 4352
#define FVSZ (64*FV_STR)           // 4608
#define FSTG (FKSZ + FVSZ + 64)    // 9024 per stage
#define FP_OFF FKSZ                // P after Q
#define FSTG_OFF (FKSZ + 4*16*FQ_STR)  // 8704: stages after Q + P
#define FL_SMEMF (FSTG_OFF + 2*FSTG)   // 26752 floats = 107008 B

__global__ __launch_bounds__(128, 2) void flash_tc(const float* __restrict__ log_temp)
{
    extern __shared__ float sm[];
    uint32_t smb = smem_u32(sm);
    float* Qs = sm;
    int tid = threadIdx.x, wid = tid >> 5, lane = tid & 31;
    float* Ps = sm + FP_OFF + wid * 16 * FQ_STR;
    int g = lane >> 2, tq = lane & 3;
    int bh = blockIdx.y, b = bh >> 4, h = bh & 15;
    int q0 = blockIdx.x * 64;

    const float* Qg  = g_Q + ((size_t)bh*Sc + q0) * HDc;
    const float* Kg  = g_K + (size_t)bh*Sc*HDc;
    const float* Vg  = g_V + (size_t)bh*Sc*HDc;
    const float* att = g_attract + bh*Sc;

    // prologue: Q + stage 0
    #pragma unroll
    for (int l = 0; l < 8; l++) {
        int c = tid + 128*l; int r = c >> 4, c4 = (c & 15) * 4;
        cpa16(smb + (uint32_t)(r*FQ_STR + c4)*4, &Qg[r*HDc + c4]);
    }
    {
        uint32_t base = smb + (uint32_t)FSTG_OFF * 4u;
        #pragma unroll
        for (int l = 0; l < 8; l++) {
            int c = tid + 128*l; int r = c >> 4, c4 = (c & 15) * 4;
            cpa16(base + (uint32_t)(r*FQ_STR + c4)*4, &Kg[(size_t)r*HDc + c4]);
            cpa16(base + (uint32_t)(FKSZ + r*FV_STR + c4)*4, &Vg[(size_t)r*HDc + c4]);
        }
        if (tid < 16) cpa16(base + (uint32_t)(FKSZ + FVSZ + tid*4)*4, &att[tid*4]);
    }
    CP_COMMIT();

    int rb = wid*16 + g;
    float reach_lo = g_reach[bh*Sc + q0 + rb];
    float reach_hi = g_reach[bh*Sc + q0 + rb + 8];
    float ip_lo = (float)(q0 + rb), ip_hi = ip_lo + 8.0f;
    float temp = __expf(log_temp[h]) + 1.0f;
    float inv_st = __fdividef(1.0f, (float)Sc * temp);

    float m_lo = -1e30f, m_hi = -1e30f, l_lo = 0.f, l_hi = 0.f;
    float O[8][4];
    #pragma unroll
    for (int nt = 0; nt < 8; nt++)
        #pragma unroll
        for (int q = 0; q < 4; q++) O[nt][q] = 0.f;

    for (int kt = 0; kt < 32; kt++) {
        int k0 = kt * 64;
        CP_WAIT(0);
        __syncthreads();
        if (kt + 1 < 32) {
            int kn = (kt + 1) * 64;
            uint32_t base = smb + (uint32_t)(FSTG_OFF + ((kt + 1) & 1) * FSTG) * 4u;
            #pragma unroll
            for (int l = 0; l < 8; l++) {
                int c = tid + 128*l; int r = c >> 4, c4 = (c & 15) * 4;
                cpa16(base + (uint32_t)(r*FQ_STR + c4)*4, &Kg[(size_t)(kn + r)*HDc + c4]);
                cpa16(base + (uint32_t)(FKSZ + r*FV_STR + c4)*4, &Vg[(size_t)(kn + r)*HDc + c4]);
            }
            if (tid < 16) cpa16(base + (uint32_t)(FKSZ + FVSZ + tid*4)*4, &att[kn + tid*4]);
        }
        CP_COMMIT();

        const float* Ks  = sm + FSTG_OFF + (kt & 1) * FSTG;
        const float* Vs  = Ks + FKSZ;
        const float* Att = Vs + FVSZ;

        // S = Q K^T
        float C[8][4];
        #pragma unroll
        for (int nt = 0; nt < 8; nt++)
            #pragma unroll
            for (int q = 0; q < 4; q++) C[nt][q] = 0.f;
        #pragma unroll
        for (int ks = 0; ks < 8; ks++) {
            unsigned a0 = __float_as_uint(Qs[rb*FQ_STR + ks*8 + tq]);
            unsigned a1 = __float_as_uint(Qs[(rb+8)*FQ_STR + ks*8 + tq]);
            unsigned a2 = __float_as_uint(Qs[rb*FQ_STR + ks*8 + tq + 4]);
            unsigned a3 = __float_as_uint(Qs[(rb+8)*FQ_STR + ks*8 + tq + 4]);
            #pragma unroll
            for (int nt = 0; nt < 8; nt++) {
                unsigned bb0 = __float_as_uint(Ks[(nt*8+g)*FQ_STR + ks*8 + tq]);
                unsigned bb1 = __float_as_uint(Ks[(nt*8+g)*FQ_STR + ks*8 + tq + 4]);
                mma8(C[nt], a0, a1, a2, a3, bb0, bb1);
            }
        }

        // row max
        float ml = -1e30f, mh = -1e30f;
        #pragma unroll
        for (int nt = 0; nt < 8; nt++) {
            #pragma unroll
            for (int q = 0; q < 4; q++) C[nt][q] *= 0.125f;
            ml = fmaxf(ml, fmaxf(C[nt][0], C[nt][1]));
            mh = fmaxf(mh, fmaxf(C[nt][2], C[nt][3]));
        }
        ml = fmaxf(ml, __shfl_xor_sync(0xffffffffu, ml, 1));
        ml = fmaxf(ml, __shfl_xor_sync(0xffffffffu, ml, 2));
        mh = fmaxf(mh, __shfl_xor_sync(0xffffffffu, mh, 1));
        mh = fmaxf(mh, __shfl_xor_sync(0xffffffffu, mh, 2));
        float mn_lo = fmaxf(m_lo, ml), mn_hi = fmaxf(m_hi, mh);
        float corr_lo = __expf(m_lo - mn_lo), corr_hi = __expf(m_hi - mn_hi);
        m_lo = mn_lo; m_hi = mn_hi;

        // p = (sigmoid(z)+1e-8) * exp(s - m)
        float rs_lo = 0.f, rs_hi = 0.f;
        #pragma unroll
        for (int nt = 0; nt < 8; nt++) {
            int jc = nt*8 + 2*tq;
            float att0 = Att[jc], att1 = Att[jc+1];
            float j0 = (float)(k0 + jc), j1 = j0 + 1.0f;
            float z00 = reach_lo + att0 - fabsf(ip_lo - j0)*inv_st;
            float z01 = reach_lo + att1 - fabsf(ip_lo - j1)*inv_st;
            float z10 = reach_hi + att0 - fabsf(ip_hi - j0)*inv_st;
            float z11 = reach_hi + att1 - fabsf(ip_hi - j1)*inv_st;
            float w00 = __fdividef(1.f, 1.f + __expf(-z00)) + 1e-8f;
            float w01 = __fdividef(1.f, 1.f + __expf(-z01)) + 1e-8f;
            float w10 = __fdividef(1.f, 1.f + __expf(-z10)) + 1e-8f;
            float w11 = __fdividef(1.f, 1.f + __expf(-z11)) + 1e-8f;
            float p00 = w00 * __expf(C[nt][0] - m_lo);
            float p01 = w01 * __expf(C[nt][1] - m_lo);
            float p10 = w10 * __expf(C[nt][2] - m_hi);
            float p11 = w11 * __expf(C[nt][3] - m_hi);
            Ps[g*FQ_STR + jc]       = p00;
            Ps[g*FQ_STR + jc + 1]   = p01;
            Ps[(g+8)*FQ_STR + jc]   = p10;
            Ps[(g+8)*FQ_STR + jc+1] = p11;
            rs_lo += p00 + p01; rs_hi += p10 + p11;
        }
        rs_lo += __shfl_xor_sync(0xffffffffu, rs_lo, 1);
        rs_lo += __shfl_xor_sync(0xffffffffu, rs_lo, 2);
        rs_hi += __shfl_xor_sync(0xffffffffu, rs_hi, 1);
        rs_hi += __shfl_xor_sync(0xffffffffu, rs_hi, 2);
        l_lo = l_lo*corr_lo + rs_lo;
        l_hi = l_hi*corr_hi + rs_hi;
        #pragma unroll
        for (int nt = 0; nt < 8; nt++) {
            O[nt][0] *= corr_lo; O[nt][1] *= corr_lo;
            O[nt][2] *= corr_hi; O[nt][3] *= corr_hi;
        }
        __syncwarp();

        // O += P V
        #pragma unroll
        for (int ks = 0; ks < 8; ks++) {
            unsigned a0 = __float_as_uint(Ps[g*FQ_STR + ks*8 + tq]);
            unsigned a1 = __float_as_uint(Ps[(g+8)*FQ_STR + ks*8 + tq]);
            unsigned a2 = __float_as_uint(Ps[g*FQ_STR + ks*8 + tq + 4]);
            unsigned a3 = __float_as_uint(Ps[(g+8)*FQ_STR + ks*8 + tq + 4]);
            #pragma unroll
            for (int nt = 0; nt < 8; nt++) {
                unsigned bb0 = __float_as_uint(Vs[(ks*8+tq)*FV_STR + nt*8 + g]);
                unsigned bb1 = __float_as_uint(Vs[(ks*8+tq+4)*FV_STR + nt*8 + g]);
                mma8(O[nt], a0, a1, a2, a3, bb0, bb1);
            }
        }
    }

    float il = __fdividef(1.f, l_lo), ih = __fdividef(1.f, l_hi);
    int r_lo = q0 + rb;
    #pragma unroll
    for (int nt = 0; nt < 8; nt++) {
        int col = h*HDc + nt*8 + 2*tq;
        float2 v0 = make_float2(O[nt][0]*il, O[nt][1]*il);
        float2 v1 = make_float2(O[nt][2]*ih, O[nt][3]*ih);
        *(float2*)&g_attn[(size_t)(b*Sc + r_lo    )*Hc + col] = v0;
        *(float2*)&g_attn[(size_t)(b*Sc + r_lo + 8)*Hc + col] = v1;
    }
}

// ---------------- residual + LayerNorm ----------------
__global__ __launch_bounds__(256) void ln_kernel(
    const float* __restrict__ hs, const float* __restrict__ gamma,
    const float* __restrict__ beta, float* __restrict__ out)
{
    int m = blockIdx.x;
    __shared__ float xs[Hc];
    __shared__ float red[8];
    __shared__ float stat[2];
    int tid = threadIdx.x;
    const float* hrow = hs + (size_t)m*Hc;
    const float* prow = g_proj + (size_t)m*Hc;

    float lsum = 0.f;
    for (int i = tid; i < Hc; i += 256) {
        float x = hrow[i] + prow[i];
        xs[i] = x;
        lsum += x;
    }
    #pragma unroll
    for (int o = 16; o > 0; o >>= 1) lsum += __shfl_xor_sync(0xffffffffu, lsum, o);
    if ((tid & 31) == 0) red[tid >> 5] = lsum;
    __syncthreads();
    if (tid == 0) {
        float s = 0.f;
        #pragma unroll
        for (int i = 0; i < 8; i++) s += red[i];
        stat[0] = s * (1.0f/(float)Hc);
    }
    __syncthreads();
    float mu = stat[0];

    float lvar = 0.f;
    for (int i = tid; i < Hc; i += 256) {
        float d = xs[i] - mu;
        lvar += d*d;
    }
    #pragma unroll
    for (int o = 16; o > 0; o >>= 1) lvar += __shfl_xor_sync(0xffffffffu, lvar, o);
    if ((tid & 31) == 0) red[tid >> 5] = lvar;
    __syncthreads();
    if (tid == 0) {
        float s = 0.f;
        #pragma unroll
        for (int i = 0; i < 8; i++) s += red[i];
        stat[1] = rsqrtf(s * (1.0f/(float)Hc) + 1e-5f);
    }
    __syncthreads();
    float rstd = stat[1];

    float* orow = out + (size_t)m*Hc;
    for (int i = tid; i < Hc; i += 256)
        orow[i] = (xs[i] - mu) * rstd * gamma[i] + beta[i];
}

// ---------------- launch ----------------
extern "C" void kernel_launch(void* const* d_in, const int* in_sizes, int n_in,
                              void* d_out, int out_size) {
    (void)in_sizes; (void)n_in; (void)out_size;
    const float* hs   = (const float*)d_in[0];
    const float* imp  = (const float*)d_in[1];
    const float* wq   = (const float*)d_in[2];
    const float* bq   = (const float*)d_in[3];
    const float* wk   = (const float*)d_in[4];
    const float* bk   = (const float*)d_in[5];
    const float* wv   = (const float*)d_in[6];
    const float* bv   = (const float*)d_in[7];
    const float* wo   = (const float*)d_in[8];
    const float* bo   = (const float*)d_in[9];
    const float* rw1  = (const float*)d_in[10];
    const float* rb1  = (const float*)d_in[11];
    const float* rw2  = (const float*)d_in[12];
    const float* rb2  = (const float*)d_in[13];
    const float* aw1  = (const float*)d_in[14];
    const float* ab1  = (const float*)d_in[15];
    const float* aw2  = (const float*)d_in[16];
    const float* ab2  = (const float*)d_in[17];
    const float* logt = (const float*)d_in[18];
    const float* lng  = (const float*)d_in[19];
    const float* lnb  = (const float*)d_in[20];
    float* out = (float*)d_out;

    const int gsmem = G_SMEMF * (int)sizeof(float);   // 75776 B
    const int fsmem = FL_SMEMF * (int)sizeof(float);  // 107008 B
    cudaFuncSetAttribute(gemm_tc<0>, cudaFuncAttributeMaxDynamicSharedMemorySize, gsmem);
    cudaFuncSetAttribute(gemm_tc<1>, cudaFuncAttributeMaxDynamicSharedMemorySize, gsmem);
    cudaFuncSetAttribute(flash_tc,   cudaFuncAttributeMaxDynamicSharedMemorySize, fsmem);

    mask_mlp_kernel<<<(Bc*Sc + 255)/256, 256>>>(imp, rw1, rb1, rw2, rb2,
                                                aw1, ab1, aw2, ab2);

    // fused QKV: grid.x = 24 (8 n-blocks per matrix x 3 matrices)
    gemm_tc<0><<<dim3(24, Mtot/128), 256, gsmem>>>(hs, wq, wk, wv, bq, bk, bv);

    flash_tc<<<dim3(Sc/64, Bc*NHc), 128, fsmem>>>(logt);

    gemm_tc<1><<<dim3(8, Mtot/128), 256, gsmem>>>(nullptr, wo, wo, wo, bo, bo, bo);

    ln_kernel<<<Mtot, 256>>>(hs, lng, lnb, out);
}